// round 17
// baseline (speedup 1.0000x reference)
#include <cuda_runtime.h>
#include <cuda_bf16.h>
#include <cstdint>

// Integration_4123168604342
// x: (T=128, B=4, E=10000, F=16) f32, dummy_index: int scalar
// out: (128, 4, 10000, 15) f32 = tanh(cumsum_T(f * dt))
//
// R17: dual bulk-async streams (R15/R16 architecture) with CHUNK=4, STAGES=4:
// smem 47KB -> 4 blocks/SM (64 warps, full occ), 4 independent copy-engine
// pipelines per SM. Same aggregate prefetch (128KB/SM reads in flight),
// finer interleave of the serialized tid0 sections.

#define T_DIM   128
#define B_DIM   4
#define E_DIM   10000
#define F_DIM   16
#define FO_DIM  15
#define BE_DIM  (B_DIM * E_DIM)               // 40000 groups
#define STRIDE_T   ((size_t)BE_DIM * F_DIM)   // 640000 floats per t (input)
#define STRIDE_TO  ((size_t)BE_DIM * FO_DIM)  // 600000 floats per t (output)

#define GROUPS_PB      32
#define THREADS        512
#define IN_ROW_FLOATS  (GROUPS_PB * F_DIM)    // 512 floats = 2048 B
#define IN_ROW_BYTES   2048
#define OUT_ROW_FLOATS (GROUPS_PB * FO_DIM)   // 480 floats = 1920 B
#define OUT_ROW_BYTES  1920
#define CHUNK          4
#define NCHUNK         (T_DIM / CHUNK)        // 32
#define STAGES         4
#define IN_STAGE_BYTES  (CHUNK * IN_ROW_BYTES)     // 8192
#define SMEM_IN_BYTES   (STAGES * IN_STAGE_BYTES)  // 32768
#define SMEM_OUT_BYTES  (2 * CHUNK * OUT_ROW_BYTES)// 15360
#define SMEM_TOTAL      (SMEM_IN_BYTES + SMEM_OUT_BYTES)  // 48128

__device__ __forceinline__ float tanh_fast(float x) {
    float y;
    asm("tanh.approx.f32 %0, %1;" : "=f"(y) : "f"(x));
    return y;
}

__device__ __forceinline__ uint32_t smem_u32(const void* p) {
    uint32_t a;
    asm("{ .reg .u64 t; cvta.to.shared.u64 t, %1; cvt.u32.u64 %0, t; }"
        : "=r"(a) : "l"(p));
    return a;
}

__device__ __forceinline__ void mbar_wait_parity(uint32_t mb, uint32_t parity) {
    uint32_t done;
    asm volatile(
        "{\n\t.reg .pred p;\n\t"
        "mbarrier.try_wait.parity.acquire.cta.shared::cta.b64 p, [%1], %2;\n\t"
        "selp.b32 %0, 1, 0, p;\n\t}"
        : "=r"(done) : "r"(mb), "r"(parity) : "memory");
    if (!done) {
        asm volatile(
            "{\n\t.reg .pred P1;\n\t"
            "WAIT_LOOP_%=:\n\t"
            "mbarrier.try_wait.parity.acquire.cta.shared::cta.b64 P1, [%0], %1, 0x989680;\n\t"
            "@P1 bra.uni WAIT_DONE_%=;\n\t"
            "bra.uni WAIT_LOOP_%=;\n\t"
            "WAIT_DONE_%=:\n\t}"
            :: "r"(mb), "r"(parity) : "memory");
    }
}

__global__ __launch_bounds__(THREADS)
void integration_kernel(const float* __restrict__ x,
                        const int* __restrict__ didx,
                        float* __restrict__ out) {
    extern __shared__ char smem[];
    float* in_base  = (float*)smem;                          // [STAGES][CHUNK][512]
    float* out_base = (float*)(smem + SMEM_IN_BYTES);        // [2][CHUNK][480]
    __shared__ uint64_t mbar[STAGES];

    const uint32_t in_addr   = smem_u32(in_base);
    const uint32_t out_addr  = smem_u32(out_base);
    const uint32_t mbar_addr = smem_u32(&mbar[0]);

    const int tid  = threadIdx.x;
    const int gsub = tid >> 4;
    const int lane = tid & 15;

    const int d = *didx;                         // uniform time channel
    const bool is_t = (lane == d);
    const int oc = lane - (lane > d ? 1 : 0);
    const int scol  = gsub * FO_DIM + oc;        // out smem column
    const int tbase = gsub * F_DIM + d;          // in smem column of t-value

    // global byte bases for this block's row spans
    const char* gin  = (const char*)x + (size_t)blockIdx.x * IN_ROW_BYTES;
    const char* gout = (const char*)out + (size_t)blockIdx.x * OUT_ROW_BYTES;

    // ---- init mbarriers ----
    if (tid == 0) {
        #pragma unroll
        for (int s = 0; s < STAGES; ++s)
            asm volatile("mbarrier.init.shared.b64 [%0], %1;"
                         :: "r"(mbar_addr + s * 8), "r"(1) : "memory");
    }
    __syncthreads();

    // issue bulk loads for chunk c into stage s (tid 0 only)
#define ISSUE_LOAD(c_, s_) do {                                                \
        const uint32_t mb_ = mbar_addr + (s_) * 8;                             \
        asm volatile("mbarrier.arrive.expect_tx.shared.b64 _, [%0], %1;"       \
                     :: "r"(mb_), "r"((uint32_t)IN_STAGE_BYTES) : "memory");   \
        _Pragma("unroll")                                                      \
        for (int k_ = 0; k_ < CHUNK; ++k_) {                                   \
            const char* g_ = gin +                                             \
                (size_t)((c_) * CHUNK + k_) * (STRIDE_T * 4);                  \
            const uint32_t ds_ = in_addr + (s_) * IN_STAGE_BYTES               \
                                 + k_ * IN_ROW_BYTES;                          \
            asm volatile(                                                      \
                "cp.async.bulk.shared::cta.global.mbarrier::complete_tx::bytes"\
                " [%0], [%1], %2, [%3];"                                       \
                :: "r"(ds_), "l"(g_), "r"((uint32_t)IN_ROW_BYTES), "r"(mb_)    \
                : "memory");                                                   \
        }                                                                      \
    } while (0)

    // ---- prologue: fill all stages ----
    if (tid == 0) {
        #pragma unroll
        for (int s = 0; s < STAGES; ++s) ISSUE_LOAD(s, s);
    }

    float acc = 0.0f;
    float prev_t = 0.0f;

    #pragma unroll 1
    for (int c = 0; c < NCHUNK; ++c) {
        const int s  = c & (STAGES - 1);
        const int ph = (c / STAGES) & 1;
        const uint32_t mb = mbar_addr + s * 8;

        // recycle the output buffer written 2 chunks ago (early, off the
        // critical path; ordered before the STS below by the first barrier).
        if (tid == 0 && c >= 2)
            asm volatile("cp.async.bulk.wait_group.read 1;" ::: "memory");

        // ---- wait input chunk ready (acquire) ----
        mbar_wait_parity(mb, (uint32_t)ph);

        const float* ib = in_base + (size_t)s * (CHUNK * IN_ROW_FLOATS);

        // fold row-0 special case: dt0 = t0 + t1  =>  prev_t = -t1
        if (c == 0) prev_t = -ib[IN_ROW_FLOATS + tbase];

        // ---- compute CHUNK rows into registers ----
        float r[CHUNK];
        #pragma unroll
        for (int k = 0; k < CHUNK; ++k) {
            const float v  = ib[k * IN_ROW_FLOATS + tid];
            const float tc = ib[k * IN_ROW_FLOATS + tbase];
            acc = fmaf(v, tc - prev_t, acc);
            r[k] = tanh_fast(acc);
            prev_t = tc;
        }

        __syncthreads();   // stage-s reads done by all; tid0's wait done

        // ---- refill this input stage for chunk c+STAGES ----
        if (tid == 0 && c + STAGES < NCHUNK) ISSUE_LOAD(c + STAGES, s);

        // ---- stage results to smem ----
        float* ob = out_base + (size_t)(c & 1) * (CHUNK * OUT_ROW_FLOATS);
        if (!is_t) {
            #pragma unroll
            for (int k = 0; k < CHUNK; ++k)
                ob[k * OUT_ROW_FLOATS + scol] = r[k];
        }
        __syncthreads();   // STS visible to issuing thread

        // ---- issue CHUNK bulk stores (1920B each) + commit ----
        if (tid == 0) {
            asm volatile("fence.proxy.async.shared::cta;" ::: "memory");
            const uint32_t s0 = out_addr + (uint32_t)((c & 1) * CHUNK * OUT_ROW_BYTES);
            #pragma unroll
            for (int k = 0; k < CHUNK; ++k) {
                const char* g = gout + (size_t)(c * CHUNK + k) * (STRIDE_TO * 4);
                asm volatile(
                    "cp.async.bulk.global.shared::cta.bulk_group [%0], [%1], %2;"
                    :: "l"(g), "r"(s0 + (uint32_t)(k * OUT_ROW_BYTES)),
                       "r"((uint32_t)OUT_ROW_BYTES)
                    : "memory");
            }
            asm volatile("cp.async.bulk.commit_group;" ::: "memory");
        }
    }

#undef ISSUE_LOAD

    // drain outstanding stores before exit
    if (tid == 0)
        asm volatile("cp.async.bulk.wait_group 0;" ::: "memory");
}

extern "C" void kernel_launch(void* const* d_in, const int* in_sizes, int n_in,
                              void* d_out, int out_size) {
    const float* x   = (const float*)d_in[0];
    const int* didx  = (const int*)d_in[1];
    float* out       = (float*)d_out;

    cudaFuncSetAttribute(integration_kernel,
                         cudaFuncAttributeMaxDynamicSharedMemorySize, SMEM_TOTAL);
    const int grid = BE_DIM / GROUPS_PB;          // 1250 exact
    integration_kernel<<<grid, THREADS, SMEM_TOTAL>>>(x, didx, out);
}